// round 7
// baseline (speedup 1.0000x reference)
#include <cuda_runtime.h>

// FlowNetC correlation: B=4, C=128, H=W=96, md=20, stride2=2, K=1, S1=1.
// out[b, iy*21+ix, y, x] = (1/128)*sum_c in1[b,c,y,x]*in2[b,c,y+dy,x+dx]
// dy=(iy-10)*2, dx=(ix-10)*2, zero outside [0,96).
//
// Thread tile: 7 dx x 8 contiguous x. K rows in smem with DIAGONAL SKEW
// (phys = e + 4*floor(e/32)) to break stride-8 bank clustering, duplicated
// (copy B shifted 2 floats) so dxg=1 windows are float4-aligned.
// Inner product uses packed fma.rn.f32x2.

#define ND 21
#define NDD 441
#define CH 128
#define HH 96
#define WW 96
#define DYG 7
#define CCK 8
#define NCHUNK 16
#define QSTP 104          // physical Q row stride (96 logical + skew pads)
#define KXP 160           // physical K row (144 logical + 4 skew pad groups)
#define KROW 1296         // 8*KXP + 16 ; /4 = 324 == 4 mod 8 (dyg slot spread)
#define ABASE 832         // after Q (8*104); group 208 == 0 mod 8
#define KREG 9072         // 7*KROW
#define BBASE 9924        // 832+9072+20 pad -> group 2481 == 1 mod 8
#define SMEMF (BBASE + KREG)   // 18996 floats
#define SMEMB (SMEMF*4)
#define NT 256
#define NACT 252          // 7 dyg * 3 dxg * 12 xg

typedef unsigned long long u64;

__device__ __forceinline__ u64 ffma2(u64 a, u64 b, u64 c) {
    u64 d;
    asm("fma.rn.f32x2 %0, %1, %2, %3;" : "=l"(d) : "l"(a), "l"(b), "l"(c));
    return d;
}
__device__ __forceinline__ int skew(int e) { return e + 4 * (e >> 5); }

__global__ void __launch_bounds__(NT, 2)
corr_kernel(const float* __restrict__ in1, const float* __restrict__ in2,
            float* __restrict__ out)
{
    extern __shared__ float smem[];
    float* Qs  = smem;            // [8][QSTP], skewed
    float* KsA = smem + ABASE;    // [7][8][KXP], skewed
    float* KsB = smem + BBASE;    // same, elements shifted left by 2

    const int y   = blockIdx.x;
    const int b   = blockIdx.y;
    const int p   = blockIdx.z;   // dy rows p*7 .. p*7+6
    const int tid = threadIdx.x;

    // Zero both K copies once (logical pads must stay zero)
    for (int i = tid; i < SMEMF - ABASE; i += NT) smem[ABASE + i] = 0.0f;

    // Thread tile: (dyg, dxg, xg); x = 8*xg .. 8*xg+7
    const bool active = tid < NACT;
    int dyg = 0, dxg = 0, xg = 0;
    if (active) {
        dyg = tid / 36;
        int r = tid - dyg * 36;
        dxg = r / 12;
        xg  = r - dxg * 12;
    }
    const int x0 = 8 * xg;
    // k window: copy + logical base so window is float4-aligned
    const float* kbase;
    int klog;
    if (dxg == 1) { kbase = KsB; klog = 8 * xg + 12; }      // B[l] = elem(l+2)
    else          { kbase = KsA; klog = 8 * xg + 28 * (dxg >> 1); }
    kbase += dyg * KROW;
    int kph[5];
    #pragma unroll
    for (int t = 0; t < 5; ++t) kph[t] = skew(klog + 4 * t);
    const int qoff = skew(8 * xg);  // = 8xg + 4*(xg>>2), 8 phys-contiguous floats

    u64 acc2[7][4];
    #pragma unroll
    for (int j = 0; j < 7; ++j)
        #pragma unroll
        for (int m = 0; m < 4; ++m) acc2[j][m] = 0ull;

    for (int cc = 0; cc < NCHUNK; ++cc) {
        __syncthreads();   // previous chunk fully consumed
        // ---- Load: 192 Q float4 + 1344 K float4 = 6 tasks/thread ----
        #pragma unroll
        for (int it = 0; it < 6; ++it) {
            int i = tid + it * NT;
            if (i < 192) {
                int c  = i / 24;
                int xq = i - c * 24;
                float4 v = *(const float4*)(in1 +
                    (((size_t)b * CH + cc * CCK + c) * HH + y) * WW + 4 * xq);
                *(float4*)(Qs + c * QSTP + 4 * xq + 4 * (xq >> 3)) = v;
            } else {
                int t   = i - 192;
                int r   = t / 192;
                int rem = t - r * 192;
                int c   = rem / 24;
                int xq  = rem - c * 24;
                int yy  = y + (p * DYG + r - 10) * 2;
                float4 v = make_float4(0.f, 0.f, 0.f, 0.f);
                if ((unsigned)yy < HH)
                    v = *(const float4*)(in2 +
                        (((size_t)b * CH + cc * CCK + c) * HH + yy) * WW + 4 * xq);
                int e  = 20 + 4 * xq;
                int pa = skew(e);
                float* ra = KsA + r * KROW + c * KXP;
                float* rb = KsB + r * KROW + c * KXP;
                *(float4*)(ra + pa) = v;
                *(float2*)(rb + skew(e - 2)) = make_float2(v.x, v.y);
                *(float2*)(rb + pa)          = make_float2(v.z, v.w);
            }
        }
        __syncthreads();

        if (active) {
            #pragma unroll 2
            for (int c = 0; c < CCK; ++c) {
                const float* qp = Qs + c * QSTP + qoff;
                ulonglong2 qv0 = *(const ulonglong2*)(qp);
                ulonglong2 qv1 = *(const ulonglong2*)(qp + 4);
                u64 q2[4] = {qv0.x, qv0.y, qv1.x, qv1.y};
                const float* kc = kbase + c * KXP;
                u64 kp2[10];
                #pragma unroll
                for (int t = 0; t < 5; ++t) {
                    ulonglong2 kv = *(const ulonglong2*)(kc + kph[t]);
                    kp2[2 * t]     = kv.x;
                    kp2[2 * t + 1] = kv.y;
                }
                #pragma unroll
                for (int j = 0; j < 7; ++j)
                    #pragma unroll
                    for (int m = 0; m < 4; ++m)
                        acc2[j][m] = ffma2(q2[m], kp2[j + m], acc2[j][m]);
            }
        }
    }

    if (active) {
        const int diy = p * DYG + dyg;
        const float s = 1.0f / 128.0f;
        #pragma unroll
        for (int j = 0; j < 7; ++j) {
            int d = diy * ND + dxg * 7 + j;
            float* o = out + (((size_t)b * NDD + d) * HH + y) * WW + x0;
            float2 r0 = *(float2*)&acc2[j][0];
            float2 r1 = *(float2*)&acc2[j][1];
            float2 r2 = *(float2*)&acc2[j][2];
            float2 r3 = *(float2*)&acc2[j][3];
            *(float4*)(o)     = make_float4(r0.x * s, r0.y * s, r1.x * s, r1.y * s);
            *(float4*)(o + 4) = make_float4(r2.x * s, r2.y * s, r3.x * s, r3.y * s);
        }
    }
}

extern "C" void kernel_launch(void* const* d_in, const int* in_sizes, int n_in,
                              void* d_out, int out_size)
{
    const float* in1 = (const float*)d_in[0];
    const float* in2 = (const float*)d_in[1];
    float* out = (float*)d_out;

    cudaFuncSetAttribute(corr_kernel,
                         cudaFuncAttributeMaxDynamicSharedMemorySize, SMEMB);
    corr_kernel<<<dim3(HH, 4, 3), NT, SMEMB>>>(in1, in2, out);
}